// round 14
// baseline (speedup 1.0000x reference)
#include <cuda_runtime.h>

#define BB 512
#define SS 1024
#define TT 48
#define MID 512
#define LN64 4.1588830833596715f

typedef unsigned long long u64;

__device__ float g_nll[BB];
__device__ float g_alpha[BB][TT];
__device__ float g_beta[BB][TT];
__device__ float g_cA[BB], g_cB[BB];

__device__ __forceinline__ u64 ffma2(u64 a, u64 b, u64 c) {
    u64 d; asm("fma.rn.f32x2 %0, %1, %2, %3;" : "=l"(d) : "l"(a), "l"(b), "l"(c)); return d;
}
__device__ __forceinline__ u64 fmul2(u64 a, u64 b) {
    u64 d; asm("mul.rn.f32x2 %0, %1, %2;" : "=l"(d) : "l"(a), "l"(b)); return d;
}
__device__ __forceinline__ u64 fadd2(u64 a, u64 b) {
    u64 d; asm("add.rn.f32x2 %0, %1, %2;" : "=l"(d) : "l"(a), "l"(b)); return d;
}
__device__ __forceinline__ u64 pack2(float lo, float hi) {
    u64 d; asm("mov.b64 %0, {%1, %2};" : "=l"(d) : "f"(lo), "f"(hi)); return d;
}
__device__ __forceinline__ void unpack2(u64 v, float& lo, float& hi) {
    asm("mov.b64 {%0, %1}, %2;" : "=f"(lo), "=f"(hi) : "l"(v));
}

// ---------------------------------------------------------------------------
// Dual-sequence, two-warp bidirectional scan.
// Blocks [0,256): forward halves of batch pair (2x, 2x+1).
// Blocks [256,512): backward halves of batch pair.
// 64-thread block: warp w lanes 0..23 own output o = 24w+lane for BOTH
// sequences (E coefficient registers shared across the pair: 24 u64).
// Per dual-step: store both q scalars, one __syncthreads, two 12xLDS.128
// matvecs (24 fma2 each), masked update per seq. Thread 24 (warp0 lane24)
// runs E=ones so its matvec results ARE sum(p) for each seq; renorm every
// 8 steps, lagged apply via shared r_sh[2]. 1/64 folded into E. Emission
// LDG ring 8 ahead per seq; exp at consume. Gold in combine kernel.
// ---------------------------------------------------------------------------
__global__ void __launch_bounds__(64) crf_fwdbwd(
    const float* __restrict__ em,       // [B,S,T]
    const float* __restrict__ trans,    // [T,T]
    const float* __restrict__ startt,   // [T]
    const float* __restrict__ endt,     // [T]
    const int* __restrict__ mask)       // [B,S] bool as int32
{
    __shared__ __align__(16) float q_sh[2][2][TT];  // [buf][seq][state]
    __shared__ float r_sh[2];

    const int tid  = threadIdx.x;
    const int wid  = tid >> 5;
    const int lane = tid & 31;
    const bool active = (lane < 24);
    const bool is_sum = (tid == 24);    // warp0 lane24: sum thread
    const int o = active ? (wid * 24 + lane) : 0;
    const bool is_fwd = (blockIdx.x < BB / 2);
    const int bb0 = (is_fwd ? blockIdx.x : (blockIdx.x - BB / 2)) * 2;

    const float inv64 = 0.015625f;

    // 24 packed coefficient pairs (48 regs), shared by both sequences.
    u64 E2[24];
#pragma unroll
    for (int u = 0; u < 24; u++) {
        float a, bb;
        if (is_fwd) {
            a  = __expf(__ldg(&trans[(2 * u) * TT + o])) * inv64;
            bb = __expf(__ldg(&trans[(2 * u + 1) * TT + o])) * inv64;
        } else {
            a  = __expf(__ldg(&trans[o * TT + 2 * u])) * inv64;
            bb = __expf(__ldg(&trans[o * TT + 2 * u + 1])) * inv64;
        }
        if (is_sum) { a = 1.0f; bb = 1.0f; }
        E2[u] = pack2(a, bb);
    }

    const float* emb0 = em + (size_t)bb0 * SS * TT;
    const float* emb1 = em + (size_t)(bb0 + 1) * SS * TT;
    const int* mk0 = mask + (size_t)bb0 * SS;
    const int* mk1 = mask + (size_t)(bb0 + 1) * SS;

    float qA, qB;                       // scalar state per seq
    float c0 = 0.0f, c1 = 0.0f;         // only tid24's are meaningful

    float eeA[8], eeB[8];
    int mmA[8], mmB[8];

    if (tid == 0) { r_sh[0] = 1.0f; r_sh[1] = 1.0f; }

    // matvec over one seq buffer: 12x LDS.128 broadcast, 4 accums x 6 fma2
    auto matvec = [&](const float* qv) -> float {
        const ulonglong2* pq = (const ulonglong2*)qv;
        u64 acc[4];
#pragma unroll
        for (int w = 0; w < 4; w++) {
            ulonglong2 v0 = pq[3 * w];
            ulonglong2 v1 = pq[3 * w + 1];
            ulonglong2 v2 = pq[3 * w + 2];
            const int e0 = 6 * w;
            u64 x = fmul2(v0.x, E2[e0]);
            x = ffma2(v0.y, E2[e0 + 1], x);
            x = ffma2(v1.x, E2[e0 + 2], x);
            x = ffma2(v1.y, E2[e0 + 3], x);
            x = ffma2(v2.x, E2[e0 + 4], x);
            x = ffma2(v2.y, E2[e0 + 5], x);
            acc[w] = x;
        }
        u64 a2 = fadd2(fadd2(acc[0], acc[1]), fadd2(acc[2], acc[3]));
        float lo, hi;
        unpack2(a2, lo, hi);
        return lo + hi;                 // sum thread: sum(p)
    };

    // one dual step; flags compile-time
    auto step = [&](int t, int k, int tn, bool apply_r, bool do_renorm,
                    bool do_pref) {
        const int buf = t & 1;
        if (active) {
            q_sh[buf][0][o] = qA;
            q_sh[buf][1][o] = qB;
        }

        const float eA = eeA[k], eB = eeB[k];
        const int mA = mmA[k], mB = mmB[k];

        __syncthreads();

        if (do_pref) {
            eeA[k] = emb0[(size_t)tn * TT + o];
            eeB[k] = emb1[(size_t)tn * TT + o];
            mmA[k] = mk0[tn];
            mmB[k] = mk1[tn];
        }

        const float sA = matvec(q_sh[buf][0]);
        const float sB = matvec(q_sh[buf][1]);

        const float qnA = sA * __expf(eA);
        const float qnB = sB * __expf(eB);
        qA = mA ? qnA : qA;
        qB = mB ? qnB : qB;

        if (apply_r) {                  // lagged renorm (bar above orders it)
            qA *= r_sh[0];
            qB *= r_sh[1];
        }
        if (do_renorm && is_sum) {      // once per 8 steps, 1 thread
            r_sh[0] = __fdividef(1.0f, sA);
            c0 += __logf(sA);
            r_sh[1] = __fdividef(1.0f, sB);
            c1 += __logf(sB);
        }
    };

    if (is_fwd) {
        qA = __expf(startt[o] + emb0[o]);
        qB = __expf(startt[o] + emb1[o]);
#pragma unroll
        for (int k = 0; k < 8; k++) {
            int t = 1 + k;
            eeA[k] = emb0[(size_t)t * TT + o];
            eeB[k] = emb1[(size_t)t * TT + o];
            mmA[k] = mk0[t];
            mmB[k] = mk1[t];
        }
        __syncthreads();                // r_sh init visible
        for (int tb = 0; tb < 64; tb++) {
            const int t0 = 1 + tb * 8;
#pragma unroll
            for (int k = 0; k < 8; k++) {
                int t = t0 + k;
                int tn = t + 8; tn = (tn < MID + 1) ? tn : MID;
                step(t, k, tn, k == 0, k == 7, true);
            }
        }
        // a = E^T alpha_512 per seq with pending renorm applied
        {
            const int buf = 513 & 1;
            if (active) {
                q_sh[buf][0][o] = qA;
                q_sh[buf][1][o] = qB;
            }
            __syncthreads();
            const float sA = matvec(q_sh[buf][0]);
            const float sB = matvec(q_sh[buf][1]);
            if (active) {
                g_alpha[bb0][o]     = sA * r_sh[0];
                g_alpha[bb0 + 1][o] = sB * r_sh[1];
            }
        }
        if (is_sum) { g_cA[bb0] = c0; g_cA[bb0 + 1] = c1; }
    } else {
        const float* eL0 = &emb0[(size_t)(SS - 1) * TT];
        const float* eL1 = &emb1[(size_t)(SS - 1) * TT];
        qA = __expf(eL0[o] + endt[o]);
        qB = __expf(eL1[o] + endt[o]);
#pragma unroll
        for (int k = 0; k < 8; k++) {
            int t = SS - 2 - k;
            eeA[k] = emb0[(size_t)t * TT + o];
            eeB[k] = emb1[(size_t)t * TT + o];
            mmA[k] = mk0[t];
            mmB[k] = mk1[t];
        }
        __syncthreads();                // r_sh init visible
        // 510 steps: 63 blocks of 8 (t=1022..519), then 6 peel (518..513)
        for (int sb = 0; sb < 63; sb++) {
            const int s0i = sb * 8;
#pragma unroll
            for (int k = 0; k < 8; k++) {
                int s = s0i + k;
                int t = SS - 2 - s;
                int tn = t - 8; tn = (tn > MID + 1) ? tn : (MID + 1);
                step(t, k, tn, k == 0, k == 7, true);
            }
        }
#pragma unroll
        for (int k = 0; k < 6; k++) {
            int t = SS - 2 - (504 + k);          // 518..513
            step(t, k, MID + 1, k == 0, false, false);
        }
        if (active) {
            g_beta[bb0][o]     = qA;
            g_beta[bb0 + 1][o] = qB;
        }
        if (is_sum) { g_cB[bb0] = c0; g_cB[bb0 + 1] = c1; }
    }
}

// ---------------------------------------------------------------------------
// Combine: gold path + mask counts (parallel over t) + alpha·beta dot + final.
// ---------------------------------------------------------------------------
__global__ void __launch_bounds__(128) crf_combine(
    const float* __restrict__ em,
    const float* __restrict__ trans,
    const float* __restrict__ startt,
    const float* __restrict__ endt,
    const int* __restrict__ tags,
    const int* __restrict__ mask)
{
    __shared__ float rg[128];
    __shared__ int   rc[128], ra[128], rb[128];
    __shared__ float dot[TT];

    const int b = blockIdx.x;
    const int tid = threadIdx.x;
    const int* tg = tags + (size_t)b * SS;
    const int* mk = mask + (size_t)b * SS;
    const float* emb = em + (size_t)b * SS * TT;

    if (tid < TT) dot[tid] = g_alpha[b][tid] * g_beta[b][tid];

    float g = 0.0f;
    int cnt = 0, nA = 0, nB = 0;
    for (int t = tid; t < SS; t += 128) {
        const int mt = mk[t] ? 1 : 0;
        cnt += mt;
        if (t == 0) {
            g += startt[tg[0]] + emb[tg[0]];
        } else if (mt) {
            g += trans[tg[t - 1] * TT + tg[t]] + emb[(size_t)t * TT + tg[t]];
            if (t <= MID) nA++; else if (t <= SS - 2) nB++;
        }
    }
    rg[tid] = g; rc[tid] = cnt; ra[tid] = nA; rb[tid] = nB;
    __syncthreads();
    for (int off = 64; off > 0; off >>= 1) {
        if (tid < off) {
            rg[tid] += rg[tid + off];
            rc[tid] += rc[tid + off];
            ra[tid] += ra[tid + off];
            rb[tid] += rb[tid + off];
        }
        __syncthreads();
    }
    if (tid == 0) {
        float s = 0.0f;
#pragma unroll
        for (int i = 0; i < TT; i++) s += dot[i];
        const float logZ = g_cA[b] + g_cB[b]
                         + (float)(ra[0] + 1 + rb[0]) * LN64 + __logf(s);
        const int len = rc[0] - 1;
        const float gold = rg[0] + endt[tg[len]];
        g_nll[b] = logZ - gold;
    }
}

// ---------------------------------------------------------------------------
__global__ void __launch_bounds__(512) crf_reduce(float* __restrict__ out)
{
    __shared__ float rs[512];
    const int tid = threadIdx.x;
    rs[tid] = g_nll[tid];
    __syncthreads();
    for (int off = 256; off > 0; off >>= 1) {
        if (tid < off) rs[tid] += rs[tid + off];
        __syncthreads();
    }
    if (tid == 0) out[0] = rs[0] / (float)BB;
}

extern "C" void kernel_launch(void* const* d_in, const int* in_sizes, int n_in,
                              void* d_out, int out_size)
{
    const float* em   = (const float*)d_in[0];
    const float* tr   = (const float*)d_in[1];
    const float* st   = (const float*)d_in[2];
    const float* en   = (const float*)d_in[3];
    const int*   tags = (const int*)d_in[4];
    const int*   mask = (const int*)d_in[5];
    float* out = (float*)d_out;

    crf_fwdbwd<<<BB, 64>>>(em, tr, st, en, mask);
    crf_combine<<<BB, 128>>>(em, tr, st, en, tags, mask);
    crf_reduce<<<1, 512>>>(out);
}

// round 15
// speedup vs baseline: 1.2732x; 1.2732x over previous
#include <cuda_runtime.h>

#define BB 512
#define SS 1024
#define TT 48
#define MID 512
#define LN64 4.1588830833596715f

typedef unsigned long long u64;

__device__ float g_nll[BB];
__device__ float g_alpha[BB][TT];
__device__ float g_beta[BB][TT];
__device__ float g_cA[BB], g_cB[BB];
__device__ unsigned int g_done;     // zero-init; self-resetting counter

__device__ __forceinline__ u64 ffma2(u64 a, u64 b, u64 c) {
    u64 d; asm("fma.rn.f32x2 %0, %1, %2, %3;" : "=l"(d) : "l"(a), "l"(b), "l"(c)); return d;
}
__device__ __forceinline__ u64 fmul2(u64 a, u64 b) {
    u64 d; asm("mul.rn.f32x2 %0, %1, %2;" : "=l"(d) : "l"(a), "l"(b)); return d;
}
__device__ __forceinline__ u64 fadd2(u64 a, u64 b) {
    u64 d; asm("add.rn.f32x2 %0, %1, %2;" : "=l"(d) : "l"(a), "l"(b)); return d;
}
__device__ __forceinline__ u64 pack2(float lo, float hi) {
    u64 d; asm("mov.b64 %0, {%1, %2};" : "=l"(d) : "f"(lo), "f"(hi)); return d;
}
__device__ __forceinline__ void unpack2(u64 v, float& lo, float& hi) {
    asm("mov.b64 {%0, %1}, %2;" : "=f"(lo), "=f"(hi) : "l"(v));
}

// ---------------------------------------------------------------------------
// Warp-per-batch bidirectional scan (validated R10 layout). Blocks [0,512)
// forward (t=1..512 + one transition-only matvec), [512,1024) backward
// (t=1022..513 after init at 1023). Thread j<24 owns output states (2j,2j+1):
// two ffma2 chains whose a-operands are the stored input pairs. Lane 24 runs
// E=ones -> sum(p) for the renorm (every 8 steps, lagged; shfl hoisted before
// the barrier, off the critical chain). 1/64 folded into E. Emission LDG
// ring 8 ahead (raw); exp at consume. Gold handled in combine kernel.
// ---------------------------------------------------------------------------
__global__ void __launch_bounds__(32) crf_fwdbwd(
    const float* __restrict__ em,       // [B,S,T]
    const float* __restrict__ trans,    // [T,T]
    const float* __restrict__ startt,   // [T]
    const float* __restrict__ endt,     // [T]
    const int* __restrict__ mask)       // [B,S] bool as int32
{
    __shared__ __align__(16) u64 p_sh[2 * 32];

    const int j  = threadIdx.x;
    const int jx = (j < 24) ? j : 23;   // safe index for loads
    const bool active = (j < 24);
    const bool is_fwd = (blockIdx.x < BB);
    const int b = is_fwd ? blockIdx.x : (blockIdx.x - BB);

    const float inv64 = 0.015625f;
    const int c0 = 2 * jx, c1 = 2 * jx + 1;

    // Two chains of packed coefficients (48 u64). Lanes >=24: ones (sum lane).
    u64 E2a[24], E2b[24];
#pragma unroll
    for (int u = 0; u < 24; u++) {
        float a0, a1, b0, b1;
        if (is_fwd) {
            a0 = __expf(__ldg(&trans[(2 * u) * TT + c0])) * inv64;
            a1 = __expf(__ldg(&trans[(2 * u + 1) * TT + c0])) * inv64;
            b0 = __expf(__ldg(&trans[(2 * u) * TT + c1])) * inv64;
            b1 = __expf(__ldg(&trans[(2 * u + 1) * TT + c1])) * inv64;
        } else {
            a0 = __expf(__ldg(&trans[c0 * TT + 2 * u])) * inv64;
            a1 = __expf(__ldg(&trans[c0 * TT + 2 * u + 1])) * inv64;
            b0 = __expf(__ldg(&trans[c1 * TT + 2 * u])) * inv64;
            b1 = __expf(__ldg(&trans[c1 * TT + 2 * u + 1])) * inv64;
        }
        if (!active) { a0 = a1 = 1.0f; b0 = b1 = 1.0f; }
        E2a[u] = pack2(a0, a1);
        E2b[u] = pack2(b0, b1);
    }

    const float* emb = em + (size_t)b * SS * TT;
    const int* mk = mask + (size_t)b * SS;

    u64 q2;
    float r_reg = 1.0f, c_loc = 0.0f;

    float2 ee[8];
    int mm[8];

    // one recursion step; all flags compile-time
    auto step = [&](int t, int k, int tn, bool apply_r, bool do_renorm,
                    bool do_pref) {
        const int buf = t & 1;
        p_sh[buf * 32 + j] = q2;

        const float2 e_k = ee[k];
        const int    m_k = mm[k];

        // hoist the renorm broadcast BEFORE the barrier (off critical chain)
        float r_bc = 1.0f;
        if (apply_r) r_bc = __shfl_sync(0xffffffffu, r_reg, 24);

        __syncwarp();

        if (do_pref) {
            ee[k] = *(const float2*)&emb[(size_t)tn * TT + 2 * jx];
            mm[k] = mk[tn];
        }

        const u64* pv = p_sh + buf * 32;
        u64 a0, a1, b0, b1;
        a0 = fmul2(pv[0], E2a[0]);
        b0 = fmul2(pv[12], E2a[12]);
        a1 = fmul2(pv[0], E2b[0]);
        b1 = fmul2(pv[12], E2b[12]);
#pragma unroll
        for (int u = 1; u < 12; u++) {
            a0 = ffma2(pv[u], E2a[u], a0);
            b0 = ffma2(pv[12 + u], E2a[12 + u], b0);
            a1 = ffma2(pv[u], E2b[u], a1);
            b1 = ffma2(pv[12 + u], E2b[12 + u], b1);
        }
        u64 acc0 = fadd2(a0, b0);
        u64 acc1 = fadd2(a1, b1);
        float l0, h0, l1, h1;
        unpack2(acc0, l0, h0);
        unpack2(acc1, l1, h1);
        const float s0 = l0 + h0;       // lane24: s0 = sum(p)
        const float s1 = l1 + h1;

        const float pe0 = __expf(e_k.x);
        const float pe1 = __expf(e_k.y);
        const u64 qn = pack2(s0 * pe0, s1 * pe1);
        q2 = m_k ? qn : q2;

        if (apply_r) q2 = fmul2(q2, pack2(r_bc, r_bc));
        if (do_renorm) {                // branch-free; only lane24's matters
            r_reg = __fdividef(1.0f, s0);
            c_loc += __logf(s0);
        }
    };

    // transition-only matvec helper (for forward tail)
    auto matvec_only = [&](int t) {
        const int buf = t & 1;
        p_sh[buf * 32 + j] = q2;
        __syncwarp();
        const u64* pv = p_sh + buf * 32;
        u64 a0, a1, b0, b1;
        a0 = fmul2(pv[0], E2a[0]);
        b0 = fmul2(pv[12], E2a[12]);
        a1 = fmul2(pv[0], E2b[0]);
        b1 = fmul2(pv[12], E2b[12]);
#pragma unroll
        for (int u = 1; u < 12; u++) {
            a0 = ffma2(pv[u], E2a[u], a0);
            b0 = ffma2(pv[12 + u], E2a[12 + u], b0);
            a1 = ffma2(pv[u], E2b[u], a1);
            b1 = ffma2(pv[12 + u], E2b[12 + u], b1);
        }
        u64 acc0 = fadd2(a0, b0);
        u64 acc1 = fadd2(a1, b1);
        float l0, h0, l1, h1;
        unpack2(acc0, l0, h0);
        unpack2(acc1, l1, h1);
        const float r = __shfl_sync(0xffffffffu, r_reg, 24);
        return make_float2((l0 + h0) * r, (l1 + h1) * r);
    };

    if (is_fwd) {
        // init alpha_0 = exp(start + e0)
        q2 = pack2(__expf(startt[c0] + emb[c0]),
                   __expf(startt[c1] + emb[c1]));
#pragma unroll
        for (int k = 0; k < 8; k++) {
            int t = 1 + k;
            ee[k] = *(const float2*)&emb[(size_t)t * TT + 2 * jx];
            mm[k] = mk[t];
        }
        for (int tb = 0; tb < 64; tb++) {
            const int t0 = 1 + tb * 8;
#pragma unroll
            for (int k = 0; k < 8; k++) {
                int t = t0 + k;
                int tn = t + 8; tn = (tn < MID + 1) ? tn : MID;
                step(t, k, tn, k == 0, k == 7, true);
            }
        }
        // a = E^T alpha_512, pending renorm (from t=512) applied
        float2 a = matvec_only(513);
        if (active) *(float2*)&g_alpha[b][2 * j] = a;
        const float cA = __shfl_sync(0xffffffffu, c_loc, 24);
        if (j == 0) g_cA[b] = cA;
    } else {
        // init v_1023 = exp(e_1023 + end)
        const float* eL = &emb[(size_t)(SS - 1) * TT];
        q2 = pack2(__expf(eL[c0] + endt[c0]),
                   __expf(eL[c1] + endt[c1]));
#pragma unroll
        for (int k = 0; k < 8; k++) {
            int t = SS - 2 - k;
            ee[k] = *(const float2*)&emb[(size_t)t * TT + 2 * jx];
            mm[k] = mk[t];
        }
        for (int sb = 0; sb < 63; sb++) {
            const int s0i = sb * 8;
#pragma unroll
            for (int k = 0; k < 8; k++) {
                int s = s0i + k;
                int t = SS - 2 - s;
                int tn = t - 8; tn = (tn > MID + 1) ? tn : (MID + 1);
                step(t, k, tn, k == 0, k == 7, true);
            }
        }
#pragma unroll
        for (int k = 0; k < 6; k++) {
            int t = SS - 2 - (504 + k);          // 518..513
            step(t, k, MID + 1, k == 0, false, false);
        }
        if (active) {
            float ql, qh;
            unpack2(q2, ql, qh);
            *(float2*)&g_beta[b][2 * j] = make_float2(ql, qh);
        }
        const float cB = __shfl_sync(0xffffffffu, c_loc, 24);
        if (j == 0) g_cB[b] = cB;
    }
}

// ---------------------------------------------------------------------------
// Combine + fused final reduction. Per-batch block: gold path + mask counts
// (parallel over t) + alpha·beta dot -> g_nll[b]. The LAST block to finish
// (atomic counter, after threadfence) reduces g_nll in a fixed-order tree
// and writes the mean to out — deterministic, and the counter self-resets.
// ---------------------------------------------------------------------------
__global__ void __launch_bounds__(128) crf_combine(
    const float* __restrict__ em,
    const float* __restrict__ trans,
    const float* __restrict__ startt,
    const float* __restrict__ endt,
    const int* __restrict__ tags,
    const int* __restrict__ mask,
    float* __restrict__ out)
{
    __shared__ float rg[128];
    __shared__ int   rc[128], ra[128], rb[128];
    __shared__ float dot[TT];
    __shared__ bool  last;

    const int b = blockIdx.x;
    const int tid = threadIdx.x;
    const int* tg = tags + (size_t)b * SS;
    const int* mk = mask + (size_t)b * SS;
    const float* emb = em + (size_t)b * SS * TT;

    if (tid < TT) dot[tid] = g_alpha[b][tid] * g_beta[b][tid];

    float g = 0.0f;
    int cnt = 0, nA = 0, nB = 0;
    for (int t = tid; t < SS; t += 128) {
        const int mt = mk[t] ? 1 : 0;
        cnt += mt;
        if (t == 0) {
            g += startt[tg[0]] + emb[tg[0]];
        } else if (mt) {
            g += trans[tg[t - 1] * TT + tg[t]] + emb[(size_t)t * TT + tg[t]];
            if (t <= MID) nA++; else if (t <= SS - 2) nB++;
        }
    }
    rg[tid] = g; rc[tid] = cnt; ra[tid] = nA; rb[tid] = nB;
    __syncthreads();
    for (int off = 64; off > 0; off >>= 1) {
        if (tid < off) {
            rg[tid] += rg[tid + off];
            rc[tid] += rc[tid + off];
            ra[tid] += ra[tid + off];
            rb[tid] += rb[tid + off];
        }
        __syncthreads();
    }
    if (tid == 0) {
        float s = 0.0f;
#pragma unroll
        for (int i = 0; i < TT; i++) s += dot[i];
        // applied matvecs: nA masked (t=1..512) + 1 transition-only + nB
        const float logZ = g_cA[b] + g_cB[b]
                         + (float)(ra[0] + 1 + rb[0]) * LN64 + __logf(s);
        const int len = rc[0] - 1;
        const float gold = rg[0] + endt[tg[len]];
        g_nll[b] = logZ - gold;
        __threadfence();
        const unsigned int ticket = atomicAdd(&g_done, 1u);
        last = (ticket == (unsigned int)(BB - 1));
    }
    __syncthreads();
    if (last) {
        // fixed-order tree over g_nll -> deterministic
        float v = g_nll[tid] + g_nll[tid + 128] + g_nll[tid + 256] + g_nll[tid + 384];
        rg[tid] = v;
        __syncthreads();
        for (int off = 64; off > 0; off >>= 1) {
            if (tid < off) rg[tid] += rg[tid + off];
            __syncthreads();
        }
        if (tid == 0) {
            out[0] = rg[0] / (float)BB;
            g_done = 0;                 // reset for next graph replay
        }
    }
}

extern "C" void kernel_launch(void* const* d_in, const int* in_sizes, int n_in,
                              void* d_out, int out_size)
{
    const float* em   = (const float*)d_in[0];
    const float* tr   = (const float*)d_in[1];
    const float* st   = (const float*)d_in[2];
    const float* en   = (const float*)d_in[3];
    const int*   tags = (const int*)d_in[4];
    const int*   mask = (const int*)d_in[5];
    float* out = (float*)d_out;

    crf_fwdbwd<<<2 * BB, 32>>>(em, tr, st, en, mask);
    crf_combine<<<BB, 128>>>(em, tr, st, en, tags, mask, out);
}